// round 14
// baseline (speedup 1.0000x reference)
#include <cuda_runtime.h>
#include <math.h>

#define BCAPS 32
#define CCAPS 32
#define HH    16
#define WW    36
#define BKK   288
#define CWW   1152
#define NB    16
#define EPSV  1e-10f
#define RSQRT2PI 0.3989422804014327f
#define K1EXP 0.84932180028801904f   /* sqrt(0.5*log2(e)) */
#define KCFOLD (RSQRT2PI / K1EXP)    /* isC = A * KCFOLD */

typedef unsigned long long ull;

// internal bkk ordering: bkk' = kq*32 + B

// ---------------- scratch ----------------------------------------------------
__device__ float  g_PTm[NB*196*BCAPS*HH];   // pose [b][xy][B][hh]
__device__ float  g_PTe[NB*BCAPS*196*HH];   // pose [b][B][xy][hh]
__device__ float  g_WTm[CCAPS*BKK*HH];      // W    [c][bkk'][hh]
__device__ float  g_AW [NB*WW*BKK];         // act window [b][ww][bkk']
__device__ float  g_RT [NB*CWW*BKK];        // R^T  [b][cww][bkk']
__device__ float  g_AP [NB*BKK*WW*CCAPS];   // a*p  [b][bkk'][ww][c]
__device__ float  g_rowsum[NB*BKK];
__device__ float2 g_EPab[NB*WW*HH*CCAPS];   // (A, B) [b][ww][h][c]
__device__ float  g_a  [NB*WW*CCAPS];

__device__ __forceinline__ float ex2f(float x) {
    float r; asm("ex2.approx.f32 %0, %1;" : "=f"(r) : "f"(x)); return r;
}
__device__ __forceinline__ ull pack2(float lo, float hi) {
    ull d; asm("mov.b64 %0, {%1, %2};" : "=l"(d) : "f"(lo), "f"(hi)); return d;
}
__device__ __forceinline__ void unpack2(float& lo, float& hi, ull v) {
    asm("mov.b64 {%0, %1}, %2;" : "=f"(lo), "=f"(hi) : "l"(v));
}
__device__ __forceinline__ ull fma2(ull a, ull b, ull c) {
    ull d; asm("fma.rn.f32x2 %0, %1, %2, %3;" : "=l"(d) : "l"(a), "l"(b), "l"(c)); return d;
}
__device__ __forceinline__ ull mul2(ull a, ull b) {
    ull d; asm("mul.rn.f32x2 %0, %1, %2;" : "=l"(d) : "l"(a), "l"(b)); return d;
}

// ---------------- fused prep kernel -------------------------------------------
// blocks [0,512): pose transpose; [512,1088): W transpose; [1088,1736): AW.
__global__ __launch_bounds__(256) void prep_kernel(
    const float* __restrict__ poses, const float* __restrict__ W,
    const float* __restrict__ act) {
    int bx = blockIdx.x, t = threadIdx.x;
    if (bx < 512) {
        int B = bx & 31, b = bx >> 5;
        __shared__ float tile[16*197];
        for (int idx = t; idx < 16*196; idx += 256) {
            int h = idx / 196, xy = idx % 196;
            tile[h*197 + xy] = poses[(b*512 + h*32 + B)*196 + xy];
        }
        __syncthreads();
        for (int idx = t; idx < 196*16; idx += 256) {
            int xy = idx >> 4, h = idx & 15;
            float v = tile[h*197 + xy];
            g_PTe[((b*32 + B)*196 + xy)*16 + h] = v;
            g_PTm[((b*196 + xy)*32 + B)*16 + h] = v;
        }
    } else if (bx < 1088) {
        int o = (bx - 512)*256 + t;     // < 147456
        int c = o / 4608;
        int r = o - c*4608;
        int bkp = r >> 4, h = r & 15;
        int kq = bkp >> 5, B = bkp & 31;
        g_WTm[o] = W[((B*9 + kq)*32 + c)*16 + h];
    } else {
        int idx = (bx - 1088)*256 + t;
        if (idx < NB*WW*BKK) {
            int b = idx / (WW*BKK);
            int r = idx % (WW*BKK);
            int ww = r / BKK, bkp = r % BKK;
            int kq = bkp >> 5, B = bkp & 31;
            g_AW[idx] = act[((b*32 + B)*14 + (ww/6)*2 + kq/3)*14 + (ww%6)*2 + kq%3];
        }
    }
}

// ---------------- warp multi-value reduction ---------------------------------
// lane l ends with the full-warp sum of value index (l>>1).
__device__ __forceinline__ float reduce16(float v[16], int lane) {
#pragma unroll
    for (int k = 0; k < 8; k++) {
        float send = (lane & 16) ? v[k] : v[k + 8];
        float r = __shfl_xor_sync(0xffffffffu, send, 16);
        v[k] = ((lane & 16) ? v[k + 8] : v[k]) + r;
    }
#pragma unroll
    for (int k = 0; k < 4; k++) {
        float send = (lane & 8) ? v[k] : v[k + 4];
        float r = __shfl_xor_sync(0xffffffffu, send, 8);
        v[k] = ((lane & 8) ? v[k + 4] : v[k]) + r;
    }
#pragma unroll
    for (int k = 0; k < 2; k++) {
        float send = (lane & 4) ? v[k] : v[k + 2];
        float r = __shfl_xor_sync(0xffffffffu, send, 4);
        v[k] = ((lane & 4) ? v[k + 2] : v[k]) + r;
    }
    {
        float send = (lane & 2) ? v[0] : v[1];
        float r = __shfl_xor_sync(0xffffffffu, send, 2);
        v[0] = ((lane & 2) ? v[1] : v[0]) + r;
    }
    return v[0] + __shfl_xor_sync(0xffffffffu, v[0], 1);
}

__device__ __forceinline__ void load16(const float* __restrict__ src, float d[16]) {
    const float4* p4 = reinterpret_cast<const float4*>(src);
    float4 a0 = p4[0], a1 = p4[1], a2 = p4[2], a3 = p4[3];
    d[0]=a0.x; d[1]=a0.y; d[2]=a0.z; d[3]=a0.w;
    d[4]=a1.x; d[5]=a1.y; d[6]=a1.z; d[7]=a1.w;
    d[8]=a2.x; d[9]=a2.y; d[10]=a2.z; d[11]=a2.w;
    d[12]=a3.x; d[13]=a3.y; d[14]=a3.z; d[15]=a3.w;
}

__device__ __forceinline__ void votes4x4(const float Wr[16], const float P[16], float V[16]) {
#pragma unroll
    for (int i = 0; i < 4; i++)
#pragma unroll
        for (int j = 0; j < 4; j++)
            V[i*4+j] = Wr[i*4+0]*P[j]   + Wr[i*4+1]*P[4+j]
                     + Wr[i*4+2]*P[8+j] + Wr[i*4+3]*P[12+j];
}

// packed votes: Vp[i,j] = Wp[i,0]*Pp[0,j] + ... (two independent lanes)
__device__ __forceinline__ void votes4x4_p(const ull Wp[16], const ull Pp[16], ull Vp[16]) {
#pragma unroll
    for (int i = 0; i < 4; i++)
#pragma unroll
        for (int j = 0; j < 4; j++)
            Vp[i*4+j] = fma2(Wp[i*4+0], Pp[j],
                        fma2(Wp[i*4+1], Pp[4+j],
                        fma2(Wp[i*4+2], Pp[8+j],
                        mul2(Wp[i*4+3], Pp[12+j]))));
}

// ---------------- M step ------------------------------------------------------
// Block = (ww, b, cg): 8 c per block, 160 threads = 5 warps.
// Warps 0-3 own kq pairs; warp 4 owns kq 8. 2 bkk per thread before the tree.
template<int FIRST>
__global__ __launch_bounds__(160, 4) void m_step_kernel(
    const float* __restrict__ beta_v, const float* __restrict__ beta_a,
    const float* __restrict__ lambda_, float* __restrict__ out) {
    const int ww = blockIdx.x, b = blockIdx.y, c0 = blockIdx.z * 8;
    const int t = threadIdx.x;
    const int warp = t >> 5, lane = t & 31;
    const int kqa = warp*2, kqb = warp*2 + 1;
    const bool has_b = (warp < 4);
    const int wx = ww/6, wy = ww%6;
    const int xa = wx*2 + kqa/3, ya = wy*2 + kqa%3;
    const int xb = wx*2 + (has_b ? kqb/3 : 0), yb = wy*2 + (has_b ? kqb%3 : 0);

    __shared__ float smP[8*5*34];
    __shared__ float smS0[8*5];
    __shared__ float cost_sm[128];

    float Pa[16], Pb[16];
    load16(&g_PTm[((b*196 + xa*14 + ya)*32 + lane)*16], Pa);
    if (has_b) load16(&g_PTm[((b*196 + xb*14 + yb)*32 + lane)*16], Pb);
    const float awa = g_AW[(b*WW + ww)*BKK + kqa*32 + lane];
    const float awb = has_b ? g_AW[(b*WW + ww)*BKK + kqb*32 + lane] : 0.f;
    const int hslot = (lane >> 1) + ((lane & 1) << 4);
    const size_t rbase = (size_t)b*CWW*BKK;

#pragma unroll 2
    for (int cc = 0; cc < 8; cc++) {
        const int c = c0 + cc;
        float rwa, rwb;
        if (FIRST) {
            const float u = 1.0f/(float)CWW;
            rwa = u * awa;
            rwb = u * awb;
        } else {
            rwa = g_RT[rbase + (size_t)(c*36 + ww)*BKK + kqa*32 + lane] * awa;
            rwb = has_b ? g_RT[rbase + (size_t)(c*36 + ww)*BKK + kqb*32 + lane] * awb : 0.f;
        }

        float Wr[16], V[16], s1[16], t2[16];
        load16(&g_WTm[(c*BKK + kqa*32 + lane)*16], Wr);
        votes4x4(Wr, Pa, V);
#pragma unroll
        for (int h = 0; h < 16; h++) {
            float rv = rwa * V[h];
            s1[h] = rv;
            t2[h] = rv * V[h];
        }
        if (has_b) {
            load16(&g_WTm[(c*BKK + kqb*32 + lane)*16], Wr);
            votes4x4(Wr, Pb, V);
#pragma unroll
            for (int h = 0; h < 16; h++) {
                float rv = rwb * V[h];
                s1[h] += rv;
                t2[h] += rv * V[h];
            }
        }

        float s0 = rwa + rwb;
#pragma unroll
        for (int o = 16; o > 0; o >>= 1) s0 += __shfl_xor_sync(0xffffffffu, s0, o);

        float S2p = reduce16(t2, lane);
        float S1p = reduce16(s1, lane);

        smP[(cc*5 + warp)*34 + hslot] = (lane & 1) ? S2p : S1p;
        if (lane == 0) smS0[cc*5 + warp] = s0;
    }
    __syncthreads();

    // finalize A: thread t<128 owns (c = t>>4, h = t&15)
    if (t < 128) {
        int cc = t >> 4, h = t & 15;
        const float* base = &smP[cc*5*34];
        float S1 = 0.f, S2 = 0.f, S0 = 0.f;
#pragma unroll
        for (int w2 = 0; w2 < 5; w2++) {
            S1 += base[w2*34 + h];
            S2 += base[w2*34 + 16 + h];
            S0 += smS0[cc*5 + w2];
        }
        float mu = S1 / S0;
        float varr = fmaxf(S2 / S0 - mu*mu, 1e-30f);
        float sg = sqrtf(varr);
        float is = 1.0f / sg;
        cost_sm[t] = logf(sg + EPSV);
        float A = is * K1EXP;
        g_EPab[((b*WW + ww)*HH + h)*CCAPS + c0 + cc] = make_float2(A, -(mu - EPSV) * A);
        if (out) out[((b*CCAPS + c0 + cc)*WW + ww)*HH + h] = mu;
    }
    __syncthreads();

    // finalize B: thread t<8 owns c
    if (t < 8) {
        int c = c0 + t;
        float cs = 0.f;
#pragma unroll
        for (int h = 0; h < 16; h++) cs += cost_sm[t*16 + h];
        float S0 = 0.f;
#pragma unroll
        for (int w2 = 0; w2 < 5; w2++) S0 += smS0[t*5 + w2];
        float total = (cs + 16.0f * beta_v[c]) * S0;
        float lam = lambda_[0];
        float a = 1.0f / (1.0f + __expf(-lam * (beta_a[c] - total)));
        g_a[(b*WW + ww)*CCAPS + c] = a;
        if (out) out[NB*CCAPS*WW*HH + (b*CCAPS + c)*WW + ww] = a;
    }
}

// ---------------- E step ------------------------------------------------------
// Block = (Bpair, b): 288 threads, 9 warps = kq; both B of the pair ride the
// SAME f32x2 lanes (fma.rn.f32x2 / mul.rn.f32x2 -> 2 MACs per FMA-pipe slot).
// (A,B) float2 read once per (h,c); isC folded into the final multiply.
__global__ __launch_bounds__(288, 2) void e_step_kernel(const float* __restrict__ W) {
    int Bp = blockIdx.x, b = blockIdx.y;
    int t = threadIdx.x;
    int warp = t >> 5, lane = t & 31;   // kq, c
    int kq = warp;
    int B0 = Bp*2, B1 = Bp*2 + 1;
    int bkk_out0 = kq*32 + B0;
    int bkk_out1 = kq*32 + B1;
    int kx = kq / 3, ky = kq % 3;

    extern __shared__ float sm[];
    float*  psm   = sm;                                    // 6272 floats
    float2* esmAB = reinterpret_cast<float2*>(sm + 6272);  // 3072 float2
    float*  a_sm  = sm + 6272 + 3072*2;                    // 192 floats

    for (int idx = t; idx < 3136; idx += 288) {
        psm[idx]        = g_PTe[(size_t)(b*32 + B0)*3136 + idx];
        psm[3136 + idx] = g_PTe[(size_t)(b*32 + B1)*3136 + idx];
    }

    float W0[16], W1[16];
    load16(&W[((B0*9 + kq)*32 + lane)*16], W0);
    load16(&W[((B1*9 + kq)*32 + lane)*16], W1);
    ull Wp[16];
#pragma unroll
    for (int q = 0; q < 16; q++) Wp[q] = pack2(W0[q], W1[q]);

    float rs0 = 0.f, rs1 = 0.f;
    for (int tile = 0; tile < 6; tile++) {       // tile == wx
        __syncthreads();
        // stage EP tile as float4 over float2 pairs (1536 float4)
        const float4* src4 = reinterpret_cast<const float4*>(
            &g_EPab[(size_t)(b*WW + tile*6)*HH*CCAPS]);
        float4* esm4 = reinterpret_cast<float4*>(esmAB);
        for (int idx = t; idx < 1536; idx += 288) esm4[idx] = src4[idx];
        for (int idx = t; idx < 192; idx += 288)
            a_sm[idx] = g_a[(b*WW + tile*6)*CCAPS + idx];
        __syncthreads();

#pragma unroll
        for (int wl = 0; wl < 6; wl++) {         // wl == wy
            const float* pp = &psm[((2*tile + kx)*14 + 2*wl + ky)*16];
            float P0[16], P1[16];
#pragma unroll
            for (int q = 0; q < 16; q++) P0[q] = pp[q];
#pragma unroll
            for (int q = 0; q < 16; q++) P1[q] = pp[3136 + q];
            ull Pp[16];
#pragma unroll
            for (int q = 0; q < 16; q++) Pp[q] = pack2(P0[q], P1[q]);
            ull Vp[16];
            votes4x4_p(Wp, Pp, Vp);

            const float2* ep = &esmAB[(wl*16)*32 + lane];
            float p0e = 0.f, p0o = 0.f, p1e = 0.f, p1o = 0.f;
#pragma unroll
            for (int h = 0; h < 16; h += 2) {
                float2 ea = ep[h*32];
                float2 eb = ep[(h+1)*32];
                ull ua = fma2(Vp[h],   pack2(ea.x, ea.x), pack2(ea.y, ea.y));
                ull ub = fma2(Vp[h+1], pack2(eb.x, eb.x), pack2(eb.y, eb.y));
                ull qa = mul2(ua, ua);
                ull qb = mul2(ub, ub);
                float q0a, q1a, q0b, q1b;
                unpack2(q0a, q1a, qa);
                unpack2(q0b, q1b, qb);
                p0e = fmaf(ea.x, ex2f(-q0a), p0e);
                p1e = fmaf(ea.x, ex2f(-q1a), p1e);
                p0o = fmaf(eb.x, ex2f(-q0b), p0o);
                p1o = fmaf(eb.x, ex2f(-q1b), p1o);
            }
            float av = a_sm[wl*32 + lane] * KCFOLD;
            float ap0 = av * (p0e + p0o);
            float ap1 = av * (p1e + p1o);
            g_AP[((size_t)(b*BKK + bkk_out0)*WW + tile*6 + wl)*CCAPS + lane] = ap0;
            g_AP[((size_t)(b*BKK + bkk_out1)*WW + tile*6 + wl)*CCAPS + lane] = ap1;
            rs0 += ap0;
            rs1 += ap1;
        }
    }
#pragma unroll
    for (int o = 16; o > 0; o >>= 1) {
        rs0 += __shfl_xor_sync(0xffffffffu, rs0, o);
        rs1 += __shfl_xor_sync(0xffffffffu, rs1, o);
    }
    if (lane == 0) {
        g_rowsum[b*BKK + bkk_out0] = rs0;
        g_rowsum[b*BKK + bkk_out1] = rs1;
    }
}

// ---------------- normalize + transpose --------------------------------------
// AP [b][bkk'][ww][c] -> RT [b][c*36+ww][bkk'], R = ap * (1/rowsum) + EPS.
// 3 ww per block: 3 independent LDG.128 in flight (MLP 3), recip amortized.
__global__ __launch_bounds__(256) void norm_kernel() {
    int wp = blockIdx.x, bt = blockIdx.y, b = blockIdx.z;
    int t = threadIdx.x;
    __shared__ float tile[3][32*33];
    __shared__ float rsin[32];
    if (t < 32) rsin[t] = 1.0f / g_rowsum[b*BKK + bt*32 + t];
    __syncthreads();

    {
        int bl = t >> 3, cq = (t & 7) * 4;
        float r = rsin[bl];
        const float* base = &g_AP[((size_t)(b*BKK + bt*32 + bl)*WW + wp*3)*CCAPS + cq];
        float4 v0 = *reinterpret_cast<const float4*>(base);
        float4 v1 = *reinterpret_cast<const float4*>(base + CCAPS);
        float4 v2 = *reinterpret_cast<const float4*>(base + 2*CCAPS);
        tile[0][bl*33 + cq+0] = fmaf(v0.x, r, EPSV);
        tile[0][bl*33 + cq+1] = fmaf(v0.y, r, EPSV);
        tile[0][bl*33 + cq+2] = fmaf(v0.z, r, EPSV);
        tile[0][bl*33 + cq+3] = fmaf(v0.w, r, EPSV);
        tile[1][bl*33 + cq+0] = fmaf(v1.x, r, EPSV);
        tile[1][bl*33 + cq+1] = fmaf(v1.y, r, EPSV);
        tile[1][bl*33 + cq+2] = fmaf(v1.z, r, EPSV);
        tile[1][bl*33 + cq+3] = fmaf(v1.w, r, EPSV);
        tile[2][bl*33 + cq+0] = fmaf(v2.x, r, EPSV);
        tile[2][bl*33 + cq+1] = fmaf(v2.y, r, EPSV);
        tile[2][bl*33 + cq+2] = fmaf(v2.z, r, EPSV);
        tile[2][bl*33 + cq+3] = fmaf(v2.w, r, EPSV);
    }
    __syncthreads();

    {
        int cc = t >> 3, bq = (t & 7) * 4;
#pragma unroll
        for (int q = 0; q < 3; q++) {
            float4 w;
            w.x = tile[q][(bq+0)*33 + cc];
            w.y = tile[q][(bq+1)*33 + cc];
            w.z = tile[q][(bq+2)*33 + cc];
            w.w = tile[q][(bq+3)*33 + cc];
            *reinterpret_cast<float4*>(
                &g_RT[((size_t)b*CWW + cc*36 + wp*3 + q)*BKK + bt*32 + bq]) = w;
        }
    }
}

// ---------------- launch ------------------------------------------------------
extern "C" void kernel_launch(void* const* d_in, const int* in_sizes, int n_in,
                              void* d_out, int out_size) {
    const float* poses  = (const float*)d_in[0];
    const float* act    = (const float*)d_in[1];
    const float* W      = (const float*)d_in[2];
    const float* beta_v = (const float*)d_in[3];
    const float* beta_a = (const float*)d_in[4];
    const float* lam    = (const float*)d_in[5];
    float* out = (float*)d_out;

    const int SMEM_E = (6272 + 3072*2 + 192) * 4;   // 50432 bytes
    static int attr_done = 0;
    if (!attr_done) {
        cudaFuncSetAttribute(e_step_kernel,
                             cudaFuncAttributeMaxDynamicSharedMemorySize, SMEM_E);
        attr_done = 1;
    }

    prep_kernel<<<1736, 256>>>(poses, W, act);

    for (int it = 0; it < 3; it++) {
        if (it == 0)
            m_step_kernel<1><<<dim3(36,16,4), 160>>>(beta_v, beta_a, lam,
                                                     (float*)nullptr);
        else
            m_step_kernel<0><<<dim3(36,16,4), 160>>>(beta_v, beta_a, lam,
                                                     it == 2 ? out : (float*)nullptr);
        if (it < 2) {
            e_step_kernel<<<dim3(16,16), 288, SMEM_E>>>(W);
            norm_kernel<<<dim3(12,9,16), 256>>>();
        }
    }
}

// round 15
// speedup vs baseline: 1.0874x; 1.0874x over previous
#include <cuda_runtime.h>
#include <math.h>

#define BCAPS 32
#define CCAPS 32
#define HH    16
#define WW    36
#define BKK   288
#define CWW   1152
#define NB    16
#define EPSV  1e-10f
#define RSQRT2PI 0.3989422804014327f
#define K1EXP 0.84932180028801904f   /* sqrt(0.5*log2(e)) */
#define KCFOLD (RSQRT2PI / K1EXP)    /* isC = A * KCFOLD */

// internal bkk ordering: bkk' = kq*32 + B

// ---------------- scratch ----------------------------------------------------
__device__ float  g_PTm[NB*196*BCAPS*HH];   // pose [b][xy][B][hh]
__device__ float  g_PTe[NB*BCAPS*196*HH];   // pose [b][B][xy][hh]
__device__ float  g_WTm[CCAPS*BKK*HH];      // W    [c][bkk'][hh]
__device__ float  g_AW [NB*WW*BKK];         // act window [b][ww][bkk']
__device__ float  g_RT [NB*CWW*BKK];        // R^T  [b][cww][bkk']
__device__ float  g_AP [NB*BKK*WW*CCAPS];   // a*p  [b][bkk'][ww][c]
__device__ float  g_rowsum[NB*BKK];
__device__ float2 g_EPab[NB*WW*HH*CCAPS];   // (A, B) [b][ww][h][c]
__device__ float  g_a  [NB*WW*CCAPS];

__device__ __forceinline__ float ex2f(float x) {
    float r; asm("ex2.approx.f32 %0, %1;" : "=f"(r) : "f"(x)); return r;
}

// ---------------- fused prep kernel -------------------------------------------
// blocks [0,512): pose transpose; [512,1088): W transpose; [1088,1736): AW.
__global__ __launch_bounds__(256) void prep_kernel(
    const float* __restrict__ poses, const float* __restrict__ W,
    const float* __restrict__ act) {
    int bx = blockIdx.x, t = threadIdx.x;
    if (bx < 512) {
        int B = bx & 31, b = bx >> 5;
        __shared__ float tile[16*197];
        for (int idx = t; idx < 16*196; idx += 256) {
            int h = idx / 196, xy = idx % 196;
            tile[h*197 + xy] = poses[(b*512 + h*32 + B)*196 + xy];
        }
        __syncthreads();
        for (int idx = t; idx < 196*16; idx += 256) {
            int xy = idx >> 4, h = idx & 15;
            float v = tile[h*197 + xy];
            g_PTe[((b*32 + B)*196 + xy)*16 + h] = v;
            g_PTm[((b*196 + xy)*32 + B)*16 + h] = v;
        }
    } else if (bx < 1088) {
        int o = (bx - 512)*256 + t;     // < 147456
        int c = o / 4608;
        int r = o - c*4608;
        int bkp = r >> 4, h = r & 15;
        int kq = bkp >> 5, B = bkp & 31;
        g_WTm[o] = W[((B*9 + kq)*32 + c)*16 + h];
    } else {
        int idx = (bx - 1088)*256 + t;
        if (idx < NB*WW*BKK) {
            int b = idx / (WW*BKK);
            int r = idx % (WW*BKK);
            int ww = r / BKK, bkp = r % BKK;
            int kq = bkp >> 5, B = bkp & 31;
            g_AW[idx] = act[((b*32 + B)*14 + (ww/6)*2 + kq/3)*14 + (ww%6)*2 + kq%3];
        }
    }
}

// ---------------- warp multi-value reduction ---------------------------------
// lane l ends with the full-warp sum of value index (l>>1).
__device__ __forceinline__ float reduce16(float v[16], int lane) {
#pragma unroll
    for (int k = 0; k < 8; k++) {
        float send = (lane & 16) ? v[k] : v[k + 8];
        float r = __shfl_xor_sync(0xffffffffu, send, 16);
        v[k] = ((lane & 16) ? v[k + 8] : v[k]) + r;
    }
#pragma unroll
    for (int k = 0; k < 4; k++) {
        float send = (lane & 8) ? v[k] : v[k + 4];
        float r = __shfl_xor_sync(0xffffffffu, send, 8);
        v[k] = ((lane & 8) ? v[k + 4] : v[k]) + r;
    }
#pragma unroll
    for (int k = 0; k < 2; k++) {
        float send = (lane & 4) ? v[k] : v[k + 2];
        float r = __shfl_xor_sync(0xffffffffu, send, 4);
        v[k] = ((lane & 4) ? v[k + 2] : v[k]) + r;
    }
    {
        float send = (lane & 2) ? v[0] : v[1];
        float r = __shfl_xor_sync(0xffffffffu, send, 2);
        v[0] = ((lane & 2) ? v[1] : v[0]) + r;
    }
    return v[0] + __shfl_xor_sync(0xffffffffu, v[0], 1);
}

__device__ __forceinline__ void load16(const float* __restrict__ src, float d[16]) {
    const float4* p4 = reinterpret_cast<const float4*>(src);
    float4 a0 = p4[0], a1 = p4[1], a2 = p4[2], a3 = p4[3];
    d[0]=a0.x; d[1]=a0.y; d[2]=a0.z; d[3]=a0.w;
    d[4]=a1.x; d[5]=a1.y; d[6]=a1.z; d[7]=a1.w;
    d[8]=a2.x; d[9]=a2.y; d[10]=a2.z; d[11]=a2.w;
    d[12]=a3.x; d[13]=a3.y; d[14]=a3.z; d[15]=a3.w;
}

__device__ __forceinline__ void votes4x4(const float Wr[16], const float P[16], float V[16]) {
#pragma unroll
    for (int i = 0; i < 4; i++)
#pragma unroll
        for (int j = 0; j < 4; j++)
            V[i*4+j] = Wr[i*4+0]*P[j]   + Wr[i*4+1]*P[4+j]
                     + Wr[i*4+2]*P[8+j] + Wr[i*4+3]*P[12+j];
}

// ---------------- M step ------------------------------------------------------
// Block = (ww, b, cg): 8 c per block, 160 threads = 5 warps.
// Warps 0-3 own kq pairs; warp 4 owns kq 8. 2 bkk per thread before the tree.
template<int FIRST>
__global__ __launch_bounds__(160, 4) void m_step_kernel(
    const float* __restrict__ beta_v, const float* __restrict__ beta_a,
    const float* __restrict__ lambda_, float* __restrict__ out) {
    const int ww = blockIdx.x, b = blockIdx.y, c0 = blockIdx.z * 8;
    const int t = threadIdx.x;
    const int warp = t >> 5, lane = t & 31;
    const int kqa = warp*2, kqb = warp*2 + 1;
    const bool has_b = (warp < 4);
    const int wx = ww/6, wy = ww%6;
    const int xa = wx*2 + kqa/3, ya = wy*2 + kqa%3;
    const int xb = wx*2 + (has_b ? kqb/3 : 0), yb = wy*2 + (has_b ? kqb%3 : 0);

    __shared__ float smP[8*5*34];
    __shared__ float smS0[8*5];
    __shared__ float cost_sm[128];

    float Pa[16], Pb[16];
    load16(&g_PTm[((b*196 + xa*14 + ya)*32 + lane)*16], Pa);
    if (has_b) load16(&g_PTm[((b*196 + xb*14 + yb)*32 + lane)*16], Pb);
    const float awa = g_AW[(b*WW + ww)*BKK + kqa*32 + lane];
    const float awb = has_b ? g_AW[(b*WW + ww)*BKK + kqb*32 + lane] : 0.f;
    const int hslot = (lane >> 1) + ((lane & 1) << 4);
    const size_t rbase = (size_t)b*CWW*BKK;

#pragma unroll 2
    for (int cc = 0; cc < 8; cc++) {
        const int c = c0 + cc;
        float rwa, rwb;
        if (FIRST) {
            const float u = 1.0f/(float)CWW;
            rwa = u * awa;
            rwb = u * awb;
        } else {
            rwa = g_RT[rbase + (size_t)(c*36 + ww)*BKK + kqa*32 + lane] * awa;
            rwb = has_b ? g_RT[rbase + (size_t)(c*36 + ww)*BKK + kqb*32 + lane] * awb : 0.f;
        }

        float Wr[16], V[16], s1[16], t2[16];
        load16(&g_WTm[(c*BKK + kqa*32 + lane)*16], Wr);
        votes4x4(Wr, Pa, V);
#pragma unroll
        for (int h = 0; h < 16; h++) {
            float rv = rwa * V[h];
            s1[h] = rv;
            t2[h] = rv * V[h];
        }
        if (has_b) {
            load16(&g_WTm[(c*BKK + kqb*32 + lane)*16], Wr);
            votes4x4(Wr, Pb, V);
#pragma unroll
            for (int h = 0; h < 16; h++) {
                float rv = rwb * V[h];
                s1[h] += rv;
                t2[h] += rv * V[h];
            }
        }

        float s0 = rwa + rwb;
#pragma unroll
        for (int o = 16; o > 0; o >>= 1) s0 += __shfl_xor_sync(0xffffffffu, s0, o);

        float S2p = reduce16(t2, lane);
        float S1p = reduce16(s1, lane);

        smP[(cc*5 + warp)*34 + hslot] = (lane & 1) ? S2p : S1p;
        if (lane == 0) smS0[cc*5 + warp] = s0;
    }
    __syncthreads();

    // finalize A: thread t<128 owns (c = t>>4, h = t&15)
    if (t < 128) {
        int cc = t >> 4, h = t & 15;
        const float* base = &smP[cc*5*34];
        float S1 = 0.f, S2 = 0.f, S0 = 0.f;
#pragma unroll
        for (int w2 = 0; w2 < 5; w2++) {
            S1 += base[w2*34 + h];
            S2 += base[w2*34 + 16 + h];
            S0 += smS0[cc*5 + w2];
        }
        float mu = S1 / S0;
        float varr = fmaxf(S2 / S0 - mu*mu, 1e-30f);
        float sg = sqrtf(varr);
        float is = 1.0f / sg;
        cost_sm[t] = logf(sg + EPSV);
        float A = is * K1EXP;
        g_EPab[((b*WW + ww)*HH + h)*CCAPS + c0 + cc] = make_float2(A, -(mu - EPSV) * A);
        if (out) out[((b*CCAPS + c0 + cc)*WW + ww)*HH + h] = mu;
    }
    __syncthreads();

    // finalize B: thread t<8 owns c
    if (t < 8) {
        int c = c0 + t;
        float cs = 0.f;
#pragma unroll
        for (int h = 0; h < 16; h++) cs += cost_sm[t*16 + h];
        float S0 = 0.f;
#pragma unroll
        for (int w2 = 0; w2 < 5; w2++) S0 += smS0[t*5 + w2];
        float total = (cs + 16.0f * beta_v[c]) * S0;
        float lam = lambda_[0];
        float a = 1.0f / (1.0f + __expf(-lam * (beta_a[c] - total)));
        g_a[(b*WW + ww)*CCAPS + c] = a;
        if (out) out[NB*CCAPS*WW*HH + (b*CCAPS + c)*WW + ww] = a;
    }
}

// ---------------- E step ------------------------------------------------------
// Block = (Bpair, b): 288 threads, 9 warps = kq; each thread handles BOTH B of
// the pair ((A,B) float2 read once, used twice; isC folded into the final
// constant multiply). lane = c. (Scalar FMA form — f32x2 packing measured slower.)
__global__ __launch_bounds__(288, 2) void e_step_kernel(const float* __restrict__ W) {
    int Bp = blockIdx.x, b = blockIdx.y;
    int t = threadIdx.x;
    int warp = t >> 5, lane = t & 31;   // kq, c
    int kq = warp;
    int B0 = Bp*2, B1 = Bp*2 + 1;
    int bkk_out0 = kq*32 + B0;
    int bkk_out1 = kq*32 + B1;
    int kx = kq / 3, ky = kq % 3;

    extern __shared__ float sm[];
    float*  psm   = sm;                                    // 6272 floats
    float2* esmAB = reinterpret_cast<float2*>(sm + 6272);  // 3072 float2
    float*  a_sm  = sm + 6272 + 3072*2;                    // 192 floats

    for (int idx = t; idx < 3136; idx += 288) {
        psm[idx]        = g_PTe[(size_t)(b*32 + B0)*3136 + idx];
        psm[3136 + idx] = g_PTe[(size_t)(b*32 + B1)*3136 + idx];
    }

    float W0[16], W1[16];
    load16(&W[((B0*9 + kq)*32 + lane)*16], W0);
    load16(&W[((B1*9 + kq)*32 + lane)*16], W1);

    float rs0 = 0.f, rs1 = 0.f;
    for (int tile = 0; tile < 6; tile++) {       // tile == wx
        __syncthreads();
        // stage EP tile as float4 over float2 pairs (1536 float4)
        const float4* src4 = reinterpret_cast<const float4*>(
            &g_EPab[(size_t)(b*WW + tile*6)*HH*CCAPS]);
        float4* esm4 = reinterpret_cast<float4*>(esmAB);
        for (int idx = t; idx < 1536; idx += 288) esm4[idx] = src4[idx];
        for (int idx = t; idx < 192; idx += 288)
            a_sm[idx] = g_a[(b*WW + tile*6)*CCAPS + idx];
        __syncthreads();

#pragma unroll
        for (int wl = 0; wl < 6; wl++) {         // wl == wy
            const float* pp = &psm[((2*tile + kx)*14 + 2*wl + ky)*16];
            float P[16], V0[16], V1[16];
#pragma unroll
            for (int q = 0; q < 16; q++) P[q] = pp[q];
            votes4x4(W0, P, V0);
#pragma unroll
            for (int q = 0; q < 16; q++) P[q] = pp[3136 + q];
            votes4x4(W1, P, V1);

            const float2* ep = &esmAB[(wl*16)*32 + lane];
            float p0e = 0.f, p0o = 0.f, p1e = 0.f, p1o = 0.f;
#pragma unroll
            for (int h = 0; h < 16; h += 2) {
                float2 ea = ep[h*32];
                float2 eb = ep[(h+1)*32];
                float u0a = fmaf(V0[h],   ea.x, ea.y);
                float u1a = fmaf(V1[h],   ea.x, ea.y);
                float u0b = fmaf(V0[h+1], eb.x, eb.y);
                float u1b = fmaf(V1[h+1], eb.x, eb.y);
                p0e = fmaf(ea.x, ex2f(-u0a*u0a), p0e);
                p1e = fmaf(ea.x, ex2f(-u1a*u1a), p1e);
                p0o = fmaf(eb.x, ex2f(-u0b*u0b), p0o);
                p1o = fmaf(eb.x, ex2f(-u1b*u1b), p1o);
            }
            float av = a_sm[wl*32 + lane] * KCFOLD;
            float ap0 = av * (p0e + p0o);
            float ap1 = av * (p1e + p1o);
            g_AP[((size_t)(b*BKK + bkk_out0)*WW + tile*6 + wl)*CCAPS + lane] = ap0;
            g_AP[((size_t)(b*BKK + bkk_out1)*WW + tile*6 + wl)*CCAPS + lane] = ap1;
            rs0 += ap0;
            rs1 += ap1;
        }
    }
#pragma unroll
    for (int o = 16; o > 0; o >>= 1) {
        rs0 += __shfl_xor_sync(0xffffffffu, rs0, o);
        rs1 += __shfl_xor_sync(0xffffffffu, rs1, o);
    }
    if (lane == 0) {
        g_rowsum[b*BKK + bkk_out0] = rs0;
        g_rowsum[b*BKK + bkk_out1] = rs1;
    }
}

// ---------------- normalize + transpose --------------------------------------
// AP [b][bkk'][ww][c] -> RT [b][c*36+ww][bkk'], R = ap * (1/rowsum) + EPS.
// 3 ww per block: 3 independent LDG.128 in flight (MLP 3), recip amortized.
__global__ __launch_bounds__(256) void norm_kernel() {
    int wp = blockIdx.x, bt = blockIdx.y, b = blockIdx.z;
    int t = threadIdx.x;
    __shared__ float tile[3][32*33];
    __shared__ float rsin[32];
    if (t < 32) rsin[t] = 1.0f / g_rowsum[b*BKK + bt*32 + t];
    __syncthreads();

    {
        int bl = t >> 3, cq = (t & 7) * 4;
        float r = rsin[bl];
        const float* base = &g_AP[((size_t)(b*BKK + bt*32 + bl)*WW + wp*3)*CCAPS + cq];
        float4 v0 = *reinterpret_cast<const float4*>(base);
        float4 v1 = *reinterpret_cast<const float4*>(base + CCAPS);
        float4 v2 = *reinterpret_cast<const float4*>(base + 2*CCAPS);
        tile[0][bl*33 + cq+0] = fmaf(v0.x, r, EPSV);
        tile[0][bl*33 + cq+1] = fmaf(v0.y, r, EPSV);
        tile[0][bl*33 + cq+2] = fmaf(v0.z, r, EPSV);
        tile[0][bl*33 + cq+3] = fmaf(v0.w, r, EPSV);
        tile[1][bl*33 + cq+0] = fmaf(v1.x, r, EPSV);
        tile[1][bl*33 + cq+1] = fmaf(v1.y, r, EPSV);
        tile[1][bl*33 + cq+2] = fmaf(v1.z, r, EPSV);
        tile[1][bl*33 + cq+3] = fmaf(v1.w, r, EPSV);
        tile[2][bl*33 + cq+0] = fmaf(v2.x, r, EPSV);
        tile[2][bl*33 + cq+1] = fmaf(v2.y, r, EPSV);
        tile[2][bl*33 + cq+2] = fmaf(v2.z, r, EPSV);
        tile[2][bl*33 + cq+3] = fmaf(v2.w, r, EPSV);
    }
    __syncthreads();

    {
        int cc = t >> 3, bq = (t & 7) * 4;
#pragma unroll
        for (int q = 0; q < 3; q++) {
            float4 w;
            w.x = tile[q][(bq+0)*33 + cc];
            w.y = tile[q][(bq+1)*33 + cc];
            w.z = tile[q][(bq+2)*33 + cc];
            w.w = tile[q][(bq+3)*33 + cc];
            *reinterpret_cast<float4*>(
                &g_RT[((size_t)b*CWW + cc*36 + wp*3 + q)*BKK + bt*32 + bq]) = w;
        }
    }
}

// ---------------- launch ------------------------------------------------------
extern "C" void kernel_launch(void* const* d_in, const int* in_sizes, int n_in,
                              void* d_out, int out_size) {
    const float* poses  = (const float*)d_in[0];
    const float* act    = (const float*)d_in[1];
    const float* W      = (const float*)d_in[2];
    const float* beta_v = (const float*)d_in[3];
    const float* beta_a = (const float*)d_in[4];
    const float* lam    = (const float*)d_in[5];
    float* out = (float*)d_out;

    const int SMEM_E = (6272 + 3072*2 + 192) * 4;   // 50432 bytes
    static int attr_done = 0;
    if (!attr_done) {
        cudaFuncSetAttribute(e_step_kernel,
                             cudaFuncAttributeMaxDynamicSharedMemorySize, SMEM_E);
        attr_done = 1;
    }

    prep_kernel<<<1736, 256>>>(poses, W, act);

    for (int it = 0; it < 3; it++) {
        if (it == 0)
            m_step_kernel<1><<<dim3(36,16,4), 160>>>(beta_v, beta_a, lam,
                                                     (float*)nullptr);
        else
            m_step_kernel<0><<<dim3(36,16,4), 160>>>(beta_v, beta_a, lam,
                                                     it == 2 ? out : (float*)nullptr);
        if (it < 2) {
            e_step_kernel<<<dim3(16,16), 288, SMEM_E>>>(W);
            norm_kernel<<<dim3(12,9,16), 256>>>();
        }
    }
}